// round 1
// baseline (speedup 1.0000x reference)
#include <cuda_runtime.h>

#define FULLMASK 0xFFFFFFFFu

// Fixed problem shape
#define BB 16
#define CC 67
#define HH 128
#define WW 128
#define PM 72
#define PR 9
#define NPLANE (HH * WW)            // 16384
#define NPIX ((size_t)BB * CC * NPLANE)

// Scratch (no cudaMalloc allowed)
__device__ float g_pooled[BB * CC];
__device__ float g_kern[BB * 81];   // [b][gidx 0..8][k2 0..8]; groups 0..7 = main, 8 = remainder

// ---------------------------------------------------------------------------
// Kernel 1: global average pool, one block per (b,c) plane
// ---------------------------------------------------------------------------
__global__ void __launch_bounds__(256) pool_kernel(const float* __restrict__ x) {
    int bc = blockIdx.x;
    const float4* xp = (const float4*)(x + (size_t)bc * NPLANE);
    int tid = threadIdx.x;
    float s = 0.f;
#pragma unroll
    for (int it = 0; it < 16; it++) {
        float4 v = xp[it * 256 + tid];
        s += (v.x + v.y) + (v.z + v.w);
    }
#pragma unroll
    for (int o = 16; o; o >>= 1) s += __shfl_xor_sync(FULLMASK, s, o);
    __shared__ float ws[8];
    if ((tid & 31) == 0) ws[tid >> 5] = s;
    __syncthreads();
    if (tid == 0) {
        float t = 0.f;
#pragma unroll
        for (int i = 0; i < 8; i++) t += ws[i];
        g_pooled[bc] = t * (1.0f / (float)NPLANE);
    }
}

// ---------------------------------------------------------------------------
// Kernel 2: dynamic kernel generation (GEMV + gate + BN + grouped softmax)
// One block per batch, 96 threads (t<72 main path, 72<=t<81 remainder path)
// ---------------------------------------------------------------------------
__global__ void __launch_bounds__(96) kgen_kernel(
    const float* __restrict__ w_main, const float* __restrict__ w_gate_main,
    const float* __restrict__ w_rem, const float* __restrict__ w_gate_rem,
    const float* __restrict__ bmg, const float* __restrict__ bmb,
    const float* __restrict__ bmm, const float* __restrict__ bmv,
    const float* __restrict__ brg, const float* __restrict__ brb,
    const float* __restrict__ brm, const float* __restrict__ brv) {
    int b = blockIdx.x;
    int t = threadIdx.x;
    __shared__ float sp[CC];
    __shared__ float raw[PM + PR];
    __shared__ float bn[PM + PR];

    if (t < CC) sp[t] = g_pooled[b * CC + t];
    __syncthreads();

    if (t < PM) {
        const float* wr = w_main + t * CC;
        float s = 0.f;
#pragma unroll 1
        for (int c = 0; c < CC; c++) s += sp[c] * wr[c];
        raw[t] = s;
    } else if (t < PM + PR) {
        int p = t - PM;
        const float* wr = w_rem + p * CC;
        float s = 0.f;
#pragma unroll 1
        for (int c = 0; c < CC; c++) s += sp[c] * wr[c];
        raw[PM + p] = s;
    }
    __syncthreads();

    if (t < PM) {
        const float* wr = w_gate_main + t * PM;
        float g = 0.f;
#pragma unroll 1
        for (int q = 0; q < PM; q++) g += raw[q] * wr[q];
        float v = raw[t] / (1.f + expf(-g));
        v = bmg[t] * (v - bmm[t]) * rsqrtf(bmv[t] + 1e-5f) + bmb[t];
        bn[t] = v;
    } else if (t < PM + PR) {
        int p = t - PM;
        const float* wr = w_gate_rem + p * PR;
        float g = 0.f;
#pragma unroll
        for (int q = 0; q < PR; q++) g += raw[PM + q] * wr[q];
        float v = raw[PM + p] / (1.f + expf(-g));
        v = brg[p] * (v - brm[p]) * rsqrtf(brv[p] + 1e-5f) + brb[p];
        bn[PM + p] = v;
    }
    __syncthreads();

    // 81 = 9 groups x 9 taps; groups of the main path and the remainder group
    // all softmax over consecutive 9-blocks.
    if (t < PM + PR) {
        int base = (t / 9) * 9;
        float m = -1e30f;
#pragma unroll
        for (int j = 0; j < 9; j++) m = fmaxf(m, bn[base + j]);
        float s = 0.f;
#pragma unroll
        for (int j = 0; j < 9; j++) s += expf(bn[base + j] - m);
        g_kern[b * 81 + t] = expf(bn[t] - m) / s;
    }
}

// ---------------------------------------------------------------------------
// Kernel 3: dynamic 3x3 conv (reflect pad) + residual.
// One block per (b,c,half-plane). 66x128 tile in smem, 256 threads,
// each thread: 4 px/row via float4 + shuffles, rolling 3-row registers.
// ---------------------------------------------------------------------------
__global__ void __launch_bounds__(256) conv_kernel(const float* __restrict__ x,
                                                   float* __restrict__ out,
                                                   float* __restrict__ out_high) {
    __shared__ float smem[66 * WW];
    int tile = blockIdx.x & 1;
    int bc = blockIdx.x >> 1;
    int b = bc / CC, c = bc % CC;
    int h0 = tile * 64;

    const float4* x4 = (const float4*)(x + (size_t)bc * NPLANE);
    float4* s4 = (float4*)smem;
    int tid = threadIdx.x;

    // Fill tile rows [h0-1, h0+64] with reflect at global edges
    for (int i = tid; i < 66 * 32; i += 256) {
        int r = i >> 5, col = i & 31;
        int gh = h0 - 1 + r;
        gh = gh < 0 ? -gh : (gh > HH - 1 ? 2 * (HH - 1) - gh : gh);
        s4[i] = x4[gh * 32 + col];
    }

    int gidx = (c < 64) ? (c >> 3) : 8;
    const float* kp = g_kern + b * 81 + gidx * 9;
    float k0 = kp[0], k1 = kp[1], k2 = kp[2];
    float k3 = kp[3], k4 = kp[4], k5 = kp[5];
    float k6 = kp[6], k7 = kp[7], k8 = kp[8];
    __syncthreads();

    int warp = tid >> 5, lane = tid & 31;
    int lr0 = warp * 8;  // 8 local rows per warp

    float4 vp, vc, vn;
    float lp, rp, lc, rc, ln, rn;

    // load smem row sr (float4 per lane) with w-reflect halo via shuffles
#define LOADROW(sr, v, lf, rt)                                   \
    do {                                                         \
        v = s4[(sr) * 32 + lane];                                \
        lf = __shfl_up_sync(FULLMASK, v.w, 1);                   \
        if (lane == 0) lf = v.y;                                 \
        rt = __shfl_down_sync(FULLMASK, v.x, 1);                 \
        if (lane == 31) rt = v.z;                                \
    } while (0)

    LOADROW(lr0, vp, lp, rp);          // row above first output row
    LOADROW(lr0 + 1, vc, lc, rc);      // first output row

    size_t obase = (size_t)bc * NPLANE + (size_t)h0 * WW;
#pragma unroll
    for (int i = 0; i < 8; i++) {
        int lr = lr0 + i;
        LOADROW(lr + 2, vn, ln, rn);

        float4 acc;
        acc.x = k0 * lp   + k1 * vp.x + k2 * vp.y;
        acc.y = k0 * vp.x + k1 * vp.y + k2 * vp.z;
        acc.z = k0 * vp.y + k1 * vp.z + k2 * vp.w;
        acc.w = k0 * vp.z + k1 * vp.w + k2 * rp;

        acc.x += k3 * lc   + k4 * vc.x + k5 * vc.y;
        acc.y += k3 * vc.x + k4 * vc.y + k5 * vc.z;
        acc.z += k3 * vc.y + k4 * vc.z + k5 * vc.w;
        acc.w += k3 * vc.z + k4 * vc.w + k5 * rc;

        acc.x += k6 * ln   + k7 * vn.x + k8 * vn.y;
        acc.y += k6 * vn.x + k7 * vn.y + k8 * vn.z;
        acc.z += k6 * vn.y + k7 * vn.z + k8 * vn.w;
        acc.w += k6 * vn.z + k7 * vn.w + k8 * rn;

        float4 hi;
        hi.x = vc.x - acc.x;
        hi.y = vc.y - acc.y;
        hi.z = vc.z - acc.z;
        hi.w = vc.w - acc.w;

        ((float4*)(out + obase + (size_t)lr * WW))[lane] = acc;
        ((float4*)(out_high + obase + (size_t)lr * WW))[lane] = hi;

        vp = vc; lp = lc; rp = rc;
        vc = vn; lc = ln; rc = rn;
    }
#undef LOADROW
}

// ---------------------------------------------------------------------------
extern "C" void kernel_launch(void* const* d_in, const int* in_sizes, int n_in,
                              void* d_out, int out_size) {
    const float* x            = (const float*)d_in[0];
    const float* w_main       = (const float*)d_in[1];
    const float* w_gate_main  = (const float*)d_in[2];
    const float* w_rem        = (const float*)d_in[3];
    const float* w_gate_rem   = (const float*)d_in[4];
    const float* bmg          = (const float*)d_in[5];
    const float* bmb          = (const float*)d_in[6];
    const float* bmm          = (const float*)d_in[7];
    const float* bmv          = (const float*)d_in[8];
    const float* brg          = (const float*)d_in[9];
    const float* brb          = (const float*)d_in[10];
    const float* brm          = (const float*)d_in[11];
    const float* brv          = (const float*)d_in[12];

    float* out      = (float*)d_out;
    float* out_high = out + NPIX;

    pool_kernel<<<BB * CC, 256>>>(x);
    kgen_kernel<<<BB, 96>>>(w_main, w_gate_main, w_rem, w_gate_rem,
                            bmg, bmb, bmm, bmv, brg, brb, brm, brv);
    conv_kernel<<<BB * CC * 2, 256>>>(x, out, out_high);
}

// round 3
// speedup vs baseline: 1.6606x; 1.6606x over previous
#include <cuda_runtime.h>

#define FULLMASK 0xFFFFFFFFu

// Fixed problem shape
#define BB 16
#define CC 67
#define HH 128
#define WW 128
#define PM 72
#define PR 9
#define NPLANE (HH * WW)            // 16384
#define NPIX ((size_t)BB * CC * NPLANE)

// Scratch (no cudaMalloc allowed)
__device__ float g_pooled[BB * CC];
__device__ float g_kern[BB * 81];   // [b][gidx 0..8][k2 0..8]; groups 0..7 = main, 8 = remainder

// ---------------------------------------------------------------------------
// Kernel 1: global average pool, one block per (b,c) plane
// ---------------------------------------------------------------------------
__global__ void __launch_bounds__(256) pool_kernel(const float* __restrict__ x) {
    int bc = blockIdx.x;
    const float4* xp = (const float4*)(x + (size_t)bc * NPLANE);
    int tid = threadIdx.x;
    float s = 0.f;
#pragma unroll
    for (int it = 0; it < 16; it++) {
        float4 v = xp[it * 256 + tid];
        s += (v.x + v.y) + (v.z + v.w);
    }
#pragma unroll
    for (int o = 16; o; o >>= 1) s += __shfl_xor_sync(FULLMASK, s, o);
    __shared__ float ws[8];
    if ((tid & 31) == 0) ws[tid >> 5] = s;
    __syncthreads();
    if (tid == 0) {
        float t = 0.f;
#pragma unroll
        for (int i = 0; i < 8; i++) t += ws[i];
        g_pooled[bc] = t * (1.0f / (float)NPLANE);
    }
}

// ---------------------------------------------------------------------------
// Kernel 2: dynamic kernel generation. One block per batch, 128 threads.
// All weights staged in smem via coalesced loads; dots fully unrolled from
// smem (odd row strides 67/72 -> conflict-free).
// ---------------------------------------------------------------------------
__global__ void __launch_bounds__(128) kgen_kernel(
    const float* __restrict__ w_main, const float* __restrict__ w_gate_main,
    const float* __restrict__ w_rem, const float* __restrict__ w_gate_rem,
    const float* __restrict__ bmg, const float* __restrict__ bmb,
    const float* __restrict__ bmm, const float* __restrict__ bmv,
    const float* __restrict__ brg, const float* __restrict__ brb,
    const float* __restrict__ brm, const float* __restrict__ brv) {
    int b = blockIdx.x;
    int t = threadIdx.x;

    __shared__ float s_wm[PM * CC];      // 4824
    __shared__ float s_wgm[PM * PM];     // 5184
    __shared__ float s_wr[PR * CC];      // 603
    __shared__ float s_wgr[PR * PR];     // 81
    __shared__ float sp[CC];
    __shared__ float raw[PM + PR];
    __shared__ float bn[PM + PR];

    for (int i = t; i < PM * CC; i += 128) s_wm[i] = w_main[i];
    for (int i = t; i < PM * PM; i += 128) s_wgm[i] = w_gate_main[i];
    for (int i = t; i < PR * CC; i += 128) s_wr[i] = w_rem[i];
    if (t < PR * PR) s_wgr[t] = w_gate_rem[t];
    if (t < CC) sp[t] = g_pooled[b * CC + t];
    __syncthreads();

    if (t < PM) {
        const float* wr = s_wm + t * CC;
        float s = 0.f;
#pragma unroll
        for (int c = 0; c < CC; c++) s += sp[c] * wr[c];
        raw[t] = s;
    } else if (t < PM + PR) {
        int p = t - PM;
        const float* wr = s_wr + p * CC;
        float s = 0.f;
#pragma unroll
        for (int c = 0; c < CC; c++) s += sp[c] * wr[c];
        raw[PM + p] = s;
    }
    __syncthreads();

    if (t < PM) {
        const float* wr = s_wgm + t * PM;
        float g = 0.f;
#pragma unroll
        for (int q = 0; q < PM; q++) g += raw[q] * wr[q];
        float v = raw[t] / (1.f + expf(-g));
        v = bmg[t] * (v - bmm[t]) * rsqrtf(bmv[t] + 1e-5f) + bmb[t];
        bn[t] = v;
    } else if (t < PM + PR) {
        int p = t - PM;
        const float* wr = s_wgr + p * PR;
        float g = 0.f;
#pragma unroll
        for (int q = 0; q < PR; q++) g += raw[PM + q] * wr[q];
        float v = raw[PM + p] / (1.f + expf(-g));
        v = brg[p] * (v - brm[p]) * rsqrtf(brv[p] + 1e-5f) + brb[p];
        bn[PM + p] = v;
    }
    __syncthreads();

    // 81 = 9 consecutive softmax groups of 9 (8 main groups + remainder)
    if (t < PM + PR) {
        int base = (t / 9) * 9;
        float m = -1e30f;
#pragma unroll
        for (int j = 0; j < 9; j++) m = fmaxf(m, bn[base + j]);
        float s = 0.f;
#pragma unroll
        for (int j = 0; j < 9; j++) s += expf(bn[base + j] - m);
        g_kern[b * 81 + t] = expf(bn[t] - m) / s;
    }
}

// ---------------------------------------------------------------------------
// Kernel 3: dynamic 3x3 conv (reflect pad) + residual.
// One block per (b,c,half-plane). 66x128 tile in smem, 256 threads.
// Streaming stores (__stcs) keep x L2-resident across the launch.
// ---------------------------------------------------------------------------
__global__ void __launch_bounds__(256) conv_kernel(const float* __restrict__ x,
                                                   float* __restrict__ out,
                                                   float* __restrict__ out_high) {
    __shared__ float smem[66 * WW];
    int tile = blockIdx.x & 1;
    int bc = blockIdx.x >> 1;
    int b = bc / CC, c = bc % CC;
    int h0 = tile * 64;

    const float4* x4 = (const float4*)(x + (size_t)bc * NPLANE);
    float4* s4 = (float4*)smem;
    int tid = threadIdx.x;

    // Fill tile rows [h0-1, h0+64] with reflect at global edges
    for (int i = tid; i < 66 * 32; i += 256) {
        int r = i >> 5, col = i & 31;
        int gh = h0 - 1 + r;
        gh = gh < 0 ? -gh : (gh > HH - 1 ? 2 * (HH - 1) - gh : gh);
        s4[i] = __ldg(&x4[gh * 32 + col]);
    }

    int gidx = (c < 64) ? (c >> 3) : 8;
    const float* kp = g_kern + b * 81 + gidx * 9;
    float k0 = kp[0], k1 = kp[1], k2 = kp[2];
    float k3 = kp[3], k4 = kp[4], k5 = kp[5];
    float k6 = kp[6], k7 = kp[7], k8 = kp[8];
    __syncthreads();

    int warp = tid >> 5, lane = tid & 31;
    int lr0 = warp * 8;  // 8 local rows per warp

    float4 vp, vc, vn;
    float lp, rp, lc, rc, ln, rn;

    // load smem row sr (float4 per lane) with w-reflect halo via shuffles
#define LOADROW(sr, v, lf, rt)                                   \
    do {                                                         \
        v = s4[(sr) * 32 + lane];                                \
        lf = __shfl_up_sync(FULLMASK, v.w, 1);                   \
        if (lane == 0) lf = v.y;                                 \
        rt = __shfl_down_sync(FULLMASK, v.x, 1);                 \
        if (lane == 31) rt = v.z;                                \
    } while (0)

    LOADROW(lr0, vp, lp, rp);          // row above first output row
    LOADROW(lr0 + 1, vc, lc, rc);      // first output row

    size_t obase = (size_t)bc * NPLANE + (size_t)h0 * WW;
#pragma unroll
    for (int i = 0; i < 8; i++) {
        int lr = lr0 + i;
        LOADROW(lr + 2, vn, ln, rn);

        float4 acc;
        acc.x = k0 * lp   + k1 * vp.x + k2 * vp.y;
        acc.y = k0 * vp.x + k1 * vp.y + k2 * vp.z;
        acc.z = k0 * vp.y + k1 * vp.z + k2 * vp.w;
        acc.w = k0 * vp.z + k1 * vp.w + k2 * rp;

        acc.x += k3 * lc   + k4 * vc.x + k5 * vc.y;
        acc.y += k3 * vc.x + k4 * vc.y + k5 * vc.z;
        acc.z += k3 * vc.y + k4 * vc.z + k5 * vc.w;
        acc.w += k3 * vc.z + k4 * vc.w + k5 * rc;

        acc.x += k6 * ln   + k7 * vn.x + k8 * vn.y;
        acc.y += k6 * vn.x + k7 * vn.y + k8 * vn.z;
        acc.z += k6 * vn.y + k7 * vn.z + k8 * vn.w;
        acc.w += k6 * vn.z + k7 * vn.w + k8 * rn;

        float4 hi;
        hi.x = vc.x - acc.x;
        hi.y = vc.y - acc.y;
        hi.z = vc.z - acc.z;
        hi.w = vc.w - acc.w;

        __stcs((float4*)(out + obase + (size_t)lr * WW) + lane, acc);
        __stcs((float4*)(out_high + obase + (size_t)lr * WW) + lane, hi);

        vp = vc; lp = lc; rp = rc;
        vc = vn; lc = ln; rc = rn;
    }
#undef LOADROW
}

// ---------------------------------------------------------------------------
extern "C" void kernel_launch(void* const* d_in, const int* in_sizes, int n_in,
                              void* d_out, int out_size) {
    const float* x            = (const float*)d_in[0];
    const float* w_main       = (const float*)d_in[1];
    const float* w_gate_main  = (const float*)d_in[2];
    const float* w_rem        = (const float*)d_in[3];
    const float* w_gate_rem   = (const float*)d_in[4];
    const float* bmg          = (const float*)d_in[5];
    const float* bmb          = (const float*)d_in[6];
    const float* bmm          = (const float*)d_in[7];
    const float* bmv          = (const float*)d_in[8];
    const float* brg          = (const float*)d_in[9];
    const float* brb          = (const float*)d_in[10];
    const float* brm          = (const float*)d_in[11];
    const float* brv          = (const float*)d_in[12];

    float* out      = (float*)d_out;
    float* out_high = out + NPIX;

    pool_kernel<<<BB * CC, 256>>>(x);
    kgen_kernel<<<BB, 128>>>(w_main, w_gate_main, w_rem, w_gate_rem,
                             bmg, bmb, bmm, bmv, brg, brb, brm, brv);
    conv_kernel<<<BB * CC * 2, 256>>>(x, out, out_high);
}